// round 17
// baseline (speedup 1.0000x reference)
#include <cuda_runtime.h>
#include <cuda_bf16.h>
#include <math_constants.h>
#include <cstdint>

// Problem constants
constexpr int BB = 4;      // batch
constexpr int NN = 4096;   // H*W tokens
constexpr int CH = 256;    // channels

// Attention tiling
constexpr int TQ = 128;    // queries per CTA (8 warps x 16)
constexpr int TK = 64;     // keys per tile
constexpr int NT = NN / TK;

// ---- device scratch (bf16 hi/lo split operands) ----
__device__ __nv_bfloat16 g_q[(size_t)BB * NN * 64];     // [token][qh(32)|ql(32)]
__device__ __nv_bfloat16 g_k[(size_t)BB * NN * 64];     // [token][kh(32)|kl(32)]
__device__ __nv_bfloat16 g_vth[(size_t)BB * 256 * NN];  // [b][channel][token] V hi (transposed)
__device__ __nv_bfloat16 g_vtl[(size_t)BB * 256 * NN];  // V lo (transposed)

// ---- attn smem layout (bytes). Padded rows: 144B = 36 words (conflict-free) ----
constexpr uint32_t OFF_Q   = 0;                    // 128 x 128B
constexpr uint32_t OFF_K0  = 16384;                // 64 x 144B = 9216
constexpr uint32_t OFF_K1  = OFF_K0 + 9216;
constexpr uint32_t OFF_VH0 = OFF_K1 + 9216;        // 256 x 144B = 36864
constexpr uint32_t OFF_VL0 = OFF_VH0 + 36864;
constexpr uint32_t OFF_VH1 = OFF_VL0 + 36864;
constexpr uint32_t OFF_VL1 = OFF_VH1 + 36864;
constexpr uint32_t SMEM_TOTAL = OFF_VL1 + 36864;   // 182272 B

// ---- proj smem (floats): sA[32][68] | sB[32][320] | sT[64][65] ----
constexpr int PROJ_SA = 32 * 68;                   // 2176
constexpr int PROJ_SB = 32 * 320;                  // 10240
constexpr int PROJ_ST = 64 * 65;                   // 4160
constexpr uint32_t PROJ_SMEM = (uint32_t)(PROJ_SA + PROJ_SB + PROJ_ST) * 4;  // 66304 B

// ---------------------------------------------------------------------------
// helpers
// ---------------------------------------------------------------------------
union F2U { float2 f; unsigned long long u; };
__device__ __forceinline__ float2 ffma2(float2 a, float2 b, float2 c) {
    F2U A, B, C, D;
    A.f = a; B.f = b; C.f = c;
    asm("fma.rn.f32x2 %0, %1, %2, %3;" : "=l"(D.u) : "l"(A.u), "l"(B.u), "l"(C.u));
    return D.f;
}

__device__ __forceinline__ uint32_t smem_u32(const void* p) {
    return (uint32_t)__cvta_generic_to_shared(const_cast<void*>(p));
}
__device__ __forceinline__ void cpa16(uint32_t dst, const void* src) {
    asm volatile("cp.async.cg.shared.global [%0], [%1], 16;" :: "r"(dst), "l"(src));
}

// mma.sync m16n8k16 row.col bf16 -> f32 accumulate (base sm_80+ PTX: compiles
// on the harness's compute_103 target, runs on the HMMA pipe)
__device__ __forceinline__ void mma_bf16(float d[4], const uint32_t a[4],
                                         uint32_t b0, uint32_t b1) {
    asm volatile(
        "mma.sync.aligned.m16n8k16.row.col.f32.bf16.bf16.f32 "
        "{%0,%1,%2,%3}, {%4,%5,%6,%7}, {%8,%9}, {%0,%1,%2,%3};"
        : "+f"(d[0]), "+f"(d[1]), "+f"(d[2]), "+f"(d[3])
        : "r"(a[0]), "r"(a[1]), "r"(a[2]), "r"(a[3]), "r"(b0), "r"(b1));
}

// split (x, y) into bf16x2 hi + bf16x2 residual-lo
__device__ __forceinline__ void bsplit(float x, float y, uint32_t& hi, uint32_t& lo) {
    __nv_bfloat162 h = __floats2bfloat162_rn(x, y);
    hi = *reinterpret_cast<uint32_t*>(&h);
    __nv_bfloat162 l = __floats2bfloat162_rn(x - __bfloat162float(h.x),
                                             y - __bfloat162float(h.y));
    lo = *reinterpret_cast<uint32_t*>(&l);
}

// ---------------------------------------------------------------------------
// Kernel 1: fused QKV projection -> bf16 hi/lo split operands.
// One CTA per 64-token m-block; ALL 5 n-blocks computed internally:
// sA loaded once per k-tile (was 5x), 5x fewer syncthreads per unit work,
// grid 256 = fully resident (0.86 wave).
// ---------------------------------------------------------------------------
__global__ __launch_bounds__(256) void proj_kernel(
    const float* __restrict__ X,
    const float* __restrict__ Wq, const float* __restrict__ bq,
    const float* __restrict__ Wk, const float* __restrict__ bk,
    const float* __restrict__ Wv, const float* __restrict__ bv)
{
    extern __shared__ float psm[];
    float* sA = psm;                       // [32][68]
    float* sB = psm + PROJ_SA;             // [32][320]
    float* sT = psm + PROJ_SA + PROJ_SB;   // [64][65]

    const int m0 = blockIdx.x * 64;
    const int t  = threadIdx.x;
    const int tmb = (t >> 4) * 4;
    const int tnb = (t & 15) * 4;

    float2 acc2[5][4][2] = {};

    for (int k0 = 0; k0 < CH; k0 += 32) {
        // A tile (64 rows x 32 cols), stored transposed
        #pragma unroll
        for (int i = 0; i < 2; i++) {
            int idx = t + i * 256;
            int m   = idx >> 3;
            int kc  = (idx & 7) * 4;
            float4 a4 = *reinterpret_cast<const float4*>(
                &X[(size_t)(m0 + m) * CH + k0 + kc]);
            sA[(kc + 0) * 68 + m] = a4.x;
            sA[(kc + 1) * 68 + m] = a4.y;
            sA[(kc + 2) * 68 + m] = a4.z;
            sA[(kc + 3) * 68 + m] = a4.w;
        }
        // B tile: all 320 output columns for this k-slab
        #pragma unroll
        for (int i = 0; i < 40; i++) {
            int idx = t + i * 256;          // 0..10239
            int kk  = idx / 320;
            int nn  = idx - kk * 320;
            int kg  = k0 + kk;
            float v;
            if (nn < 32)       v = Wq[kg * 32 + nn];
            else if (nn < 64)  v = Wk[kg * 32 + (nn - 32)];
            else               v = Wv[kg * 256 + (nn - 64)];
            sB[kk * 320 + nn] = v;
        }
        __syncthreads();

        #pragma unroll
        for (int k = 0; k < 32; k++) {
            float4 a4 = *reinterpret_cast<const float4*>(&sA[k * 68 + tmb]);
            float av[4] = {a4.x, a4.y, a4.z, a4.w};
            #pragma unroll
            for (int nb = 0; nb < 5; nb++) {
                float4 b4 = *reinterpret_cast<const float4*>(
                    &sB[k * 320 + nb * 64 + tnb]);
                float2 b01 = make_float2(b4.x, b4.y);
                float2 b23 = make_float2(b4.z, b4.w);
                #pragma unroll
                for (int i = 0; i < 4; i++) {
                    float2 aa = make_float2(av[i], av[i]);
                    acc2[nb][i][0] = ffma2(aa, b01, acc2[nb][i][0]);
                    acc2[nb][i][1] = ffma2(aa, b23, acc2[nb][i][1]);
                }
            }
        }
        __syncthreads();
    }

    // ---- nb = 0 epilogue: q/k (scalar stores, small volume) ----
    #pragma unroll
    for (int j = 0; j < 4; j++) {
        int n = tnb + j;
        float bias = (n < 32) ? bq[n] : bk[n - 32];
        #pragma unroll
        for (int i = 0; i < 4; i++) {
            int m = m0 + tmb + i;
            float val = (j & 1) ? ((j < 2) ? acc2[0][i][0].y : acc2[0][i][1].y)
                                : ((j < 2) ? acc2[0][i][0].x : acc2[0][i][1].x);
            val += bias;
            __nv_bfloat16 h  = __float2bfloat16(val);
            __nv_bfloat16 lo = __float2bfloat16(val - __bfloat162float(h));
            if (n < 32) {
                g_q[(size_t)m * 64 + n]      = h;
                g_q[(size_t)m * 64 + 32 + n] = lo;
            } else {
                int c = n - 32;
                g_k[(size_t)m * 64 + c]      = h;
                g_k[(size_t)m * 64 + 32 + c] = lo;
            }
        }
    }

    // ---- nb = 1..4: V epilogue via smem transpose, coalesced 16B stores ----
    const int bb   = m0 >> 12;
    const int tok0 = m0 & 4095;
    const int tokg = t & 7;
    for (int nb = 1; nb < 5; nb++) {
        #pragma unroll
        for (int j = 0; j < 4; j++) {
            int n = nb * 64 + tnb + j;
            float bias = bv[n - 64];
            #pragma unroll
            for (int i = 0; i < 4; i++) {
                float val = (j & 1) ? ((j < 2) ? acc2[nb][i][0].y : acc2[nb][i][1].y)
                                    : ((j < 2) ? acc2[nb][i][0].x : acc2[nb][i][1].x);
                sT[(tmb + i) * 65 + tnb + j] = val + bias;
            }
        }
        __syncthreads();

        #pragma unroll
        for (int half = 0; half < 2; half++) {
            const int cl = (t >> 3) + half * 32;       // local channel 0..63
            const int c  = (nb - 1) * 64 + cl;         // global channel
            uint32_t hi4[4], lo4[4];
            #pragma unroll
            for (int u = 0; u < 4; u++) {
                float v0 = sT[(tokg * 8 + 2 * u) * 65 + cl];
                float v1 = sT[(tokg * 8 + 2 * u + 1) * 65 + cl];
                bsplit(v0, v1, hi4[u], lo4[u]);
            }
            const size_t o = ((size_t)(bb * 256 + c)) * NN + tok0 + tokg * 8;
            *reinterpret_cast<uint4*>(&g_vth[o]) =
                make_uint4(hi4[0], hi4[1], hi4[2], hi4[3]);
            *reinterpret_cast<uint4*>(&g_vtl[o]) =
                make_uint4(lo4[0], lo4[1], lo4[2], lo4[3]);
        }
        __syncthreads();   // sT reads done before next nb overwrites
    }
}

// ---------------------------------------------------------------------------
// Kernel 2: flash attention via mma.sync (HMMA), FA2 layout.
// EXACT R13 version (session-best attn: 328us, tensor 58%): 8 warps x 16q,
// scalar LDS fragment loads (deep sw-pipelining), double-buffered K/V planes.
// ---------------------------------------------------------------------------
__global__ __launch_bounds__(256, 1) void attn_kernel(
    const float* __restrict__ X,
    const float* __restrict__ gamma_p,
    float* __restrict__ out)
{
    extern __shared__ __align__(16) char smem[];
    const int tid  = threadIdx.x;
    const int wid  = tid >> 5;
    const int lane = tid & 31;
    const int gid  = lane >> 2;   // 0..7
    const int tg   = lane & 3;    // 0..3
    const int b    = blockIdx.x & 3;
    const int q0   = (blockIdx.x >> 2) * TQ;

    const uint32_t offK[2]  = { OFF_K0, OFF_K1 };
    const uint32_t offVH[2] = { OFF_VH0, OFF_VH1 };
    const uint32_t offVL[2] = { OFF_VL0, OFF_VL1 };

    const uint32_t sbase = smem_u32(smem);

    // padded-row plane loader: rows of 128B data -> 144B pitch
    auto load_pad = [&](uint32_t dstOff, const __nv_bfloat16* src,
                        int rows, size_t strideElems) {
        for (int i = tid; i < rows * 8; i += 256) {
            int r = i >> 3, c = i & 7;
            cpa16(sbase + dstOff + (uint32_t)(r * 144 + c * 16),
                  src + (size_t)r * strideElems + c * 8);
        }
    };

    // ---- preload Q (unpadded 128B rows) + tile 0, one commit group ----
    {
        const __nv_bfloat16* qsrc = g_q + (size_t)(b * NN + q0) * 64;
        for (int i = tid; i < TQ * 8; i += 256) {
            int r = i >> 3, c = i & 7;
            cpa16(sbase + OFF_Q + (uint32_t)(r * 128 + c * 16),
                  qsrc + (size_t)r * 64 + c * 8);
        }
        load_pad(OFF_K0,  g_k   + (size_t)(b * NN) * 64, TK, 64);
        load_pad(OFF_VH0, g_vth + (size_t)(b * 256) * NN, 256, NN);
        load_pad(OFF_VL0, g_vtl + (size_t)(b * 256) * NN, 256, NN);
        asm volatile("cp.async.commit_group;");
    }

    float of[32][4];
    #pragma unroll
    for (int nf = 0; nf < 32; nf++)
        #pragma unroll
        for (int e = 0; e < 4; e++) of[nf][e] = 0.f;

    uint32_t qh[2][4], ql[2][4];   // Q A-frags (set at tile 0)
    float lr0 = 0.f, lr1 = 0.f;    // running row sums (rows gid, gid+8)

    for (int tt = 0; tt < NT; tt++) {
        const int cur = tt & 1;

        // prefetch tile tt+1 into the other buffer
        if (tt + 1 < NT) {
            const int j1 = (tt + 1) * TK;
            load_pad(offK[cur ^ 1],  g_k   + (size_t)(b * NN + j1) * 64, TK, 64);
            load_pad(offVH[cur ^ 1], g_vth + (size_t)(b * 256) * NN + j1, 256, NN);
            load_pad(offVL[cur ^ 1], g_vtl + (size_t)(b * 256) * NN + j1, 256, NN);
            asm volatile("cp.async.commit_group;");
            asm volatile("cp.async.wait_group 1;");
        } else {
            asm volatile("cp.async.wait_group 0;");
        }
        __syncthreads();   // tile tt visible to all warps

        if (tt == 0) {
            // load Q A-fragments once (rows wid*16+gid, +8; 32-word rows)
            const uint32_t* q32 = (const uint32_t*)(smem + OFF_Q);
            const int r0 = (wid * 16 + gid) * 32;
            const int r1 = r0 + 8 * 32;
            #pragma unroll
            for (int kc = 0; kc < 2; kc++) {
                qh[kc][0] = q32[r0 + 8 * kc + tg];
                qh[kc][1] = q32[r1 + 8 * kc + tg];
                qh[kc][2] = q32[r0 + 8 * kc + tg + 4];
                qh[kc][3] = q32[r1 + 8 * kc + tg + 4];
                ql[kc][0] = q32[r0 + 16 + 8 * kc + tg];
                ql[kc][1] = q32[r1 + 16 + 8 * kc + tg];
                ql[kc][2] = q32[r0 + 16 + 8 * kc + tg + 4];
                ql[kc][3] = q32[r1 + 16 + 8 * kc + tg + 4];
            }
        }

        // ---- QK^T: S(16x64) = qh*kh + qh*kl + ql*kh ----
        float sf[8][4];
        #pragma unroll
        for (int nf = 0; nf < 8; nf++)
            #pragma unroll
            for (int e = 0; e < 4; e++) sf[nf][e] = 0.f;

        const uint32_t* kw = (const uint32_t*)(smem + offK[cur]);
        #pragma unroll
        for (int nf = 0; nf < 8; nf++) {
            const uint32_t* kr = kw + (nf * 8 + gid) * 36;
            uint32_t kh0 = kr[tg],      kh1 = kr[tg + 4],
                     kh2 = kr[tg + 8],  kh3 = kr[tg + 12];
            uint32_t kl0 = kr[tg + 16], kl1 = kr[tg + 20],
                     kl2 = kr[tg + 24], kl3 = kr[tg + 28];
            mma_bf16(sf[nf], qh[0], kh0, kh1);
            mma_bf16(sf[nf], qh[1], kh2, kh3);
            mma_bf16(sf[nf], qh[0], kl0, kl1);
            mma_bf16(sf[nf], qh[1], kl2, kl3);
            mma_bf16(sf[nf], ql[0], kh0, kh1);
            mma_bf16(sf[nf], ql[1], kh2, kh3);
        }

        // ---- softmax numerator + row-sum accumulation ----
        #pragma unroll
        for (int nf = 0; nf < 8; nf++) {
            sf[nf][0] = __expf(sf[nf][0]);
            sf[nf][1] = __expf(sf[nf][1]);
            sf[nf][2] = __expf(sf[nf][2]);
            sf[nf][3] = __expf(sf[nf][3]);
            lr0 += sf[nf][0] + sf[nf][1];
            lr1 += sf[nf][2] + sf[nf][3];
        }

        // ---- P -> A-fragments (hi + residual lo), S-frag identity remap ----
        uint32_t ahi[4][4], alo[4][4];
        #pragma unroll
        for (int kc = 0; kc < 4; kc++) {
            const float* p0 = sf[2 * kc];
            const float* p1 = sf[2 * kc + 1];
            bsplit(p0[0], p0[1], ahi[kc][0], alo[kc][0]);
            bsplit(p0[2], p0[3], ahi[kc][1], alo[kc][1]);
            bsplit(p1[0], p1[1], ahi[kc][2], alo[kc][2]);
            bsplit(p1[2], p1[3], ahi[kc][3], alo[kc][3]);
        }

        // ---- PV: O(16x256) += ph*vh + ph*vl + pl*vh ----
        const uint32_t* vh = (const uint32_t*)(smem + offVH[cur]);
        const uint32_t* vl = (const uint32_t*)(smem + offVL[cur]);
        #pragma unroll
        for (int nf = 0; nf < 32; nf++) {
            const uint32_t* vhr = vh + (nf * 8 + gid) * 36;
            const uint32_t* vlr = vl + (nf * 8 + gid) * 36;
            #pragma unroll
            for (int kc = 0; kc < 4; kc++) {
                uint32_t b0 = vhr[8 * kc + tg], b1 = vhr[8 * kc + tg + 4];
                uint32_t c0 = vlr[8 * kc + tg], c1 = vlr[8 * kc + tg + 4];
                mma_bf16(of[nf], ahi[kc], b0, b1);
                mma_bf16(of[nf], ahi[kc], c0, c1);
                mma_bf16(of[nf], alo[kc], b0, b1);
            }
        }
        __syncthreads();   // all warps done with buffer cur -> safe to refill
    }

    // ---- epilogue: out = gamma * O / l + X ----
    lr0 += __shfl_xor_sync(0xffffffffu, lr0, 1);
    lr0 += __shfl_xor_sync(0xffffffffu, lr0, 2);
    lr1 += __shfl_xor_sync(0xffffffffu, lr1, 1);
    lr1 += __shfl_xor_sync(0xffffffffu, lr1, 2);

    const float gm = *gamma_p;
    const float s0 = gm / lr0;
    const float s1 = gm / lr1;

    const int qa = q0 + wid * 16 + gid;
    const size_t ra = (size_t)(b * NN + qa) * CH;
    const size_t rb = ra + (size_t)8 * CH;

    #pragma unroll
    for (int nf = 0; nf < 32; nf++) {
        const int c = nf * 8 + 2 * tg;
        float2 xa = *reinterpret_cast<const float2*>(&X[ra + c]);
        float2 xb = *reinterpret_cast<const float2*>(&X[rb + c]);
        float2 oa, ob;
        oa.x = fmaf(of[nf][0], s0, xa.x);
        oa.y = fmaf(of[nf][1], s0, xa.y);
        ob.x = fmaf(of[nf][2], s1, xb.x);
        ob.y = fmaf(of[nf][3], s1, xb.y);
        *reinterpret_cast<float2*>(&out[ra + c]) = oa;
        *reinterpret_cast<float2*>(&out[rb + c]) = ob;
    }
}

// ---------------------------------------------------------------------------
// Launch
// ---------------------------------------------------------------------------
extern "C" void kernel_launch(void* const* d_in, const int* in_sizes, int n_in,
                              void* d_out, int out_size)
{
    const float* X     = (const float*)d_in[0];
    const float* Wq    = (const float*)d_in[1];
    const float* bq    = (const float*)d_in[2];
    const float* Wk    = (const float*)d_in[3];
    const float* bk    = (const float*)d_in[4];
    const float* Wv    = (const float*)d_in[5];
    const float* bv    = (const float*)d_in[6];
    const float* gamma = (const float*)d_in[7];
    float* out = (float*)d_out;

    static bool cfgd = false;
    if (!cfgd) {
        (void)cudaFuncSetAttribute(proj_kernel,
                                   cudaFuncAttributeMaxDynamicSharedMemorySize,
                                   (int)PROJ_SMEM);
        (void)cudaFuncSetAttribute(attn_kernel,
                                   cudaFuncAttributeMaxDynamicSharedMemorySize,
                                   (int)SMEM_TOTAL);
        cfgd = true;
    }

    proj_kernel<<<(BB * NN) / 64, 256, PROJ_SMEM>>>(X, Wq, bq, Wk, bk, Wv, bv);

    dim3 g2((NN / TQ) * BB, 1);          // 128 CTAs: blockIdx.x = qtile*4 + b
    attn_kernel<<<g2, 256, SMEM_TOTAL>>>(X, gamma, out);
}